// round 11
// baseline (speedup 1.0000x reference)
#include <cuda_runtime.h>
#include <math.h>
#include <stdint.h>

// LIF cell scan: v = v*sigmoid(decay)*(1-z) + x_t ; z = (v - 0.5 > 0)
// x [B,T,H] f32 -> spikes [B,T,H] f32.  B=512, T=512, H=256.
//
// R11 (= R10 resubmit; prior round died to container flake, not kernel):
// warp-per-row + 32-stage cp.async SMEM ring for the x read stream.
// cp.async is non-droppable and register-free: each warp holds up to 32KB
// of reads in flight (~16MB chip-wide) vs the ~8MB register-buffer cap of
// earlier rounds. Thread-local slots -> only per-thread wait_group needed.
// Arithmetic association identical to the rel_err=0 versions.

#define B_DIM 512
#define T_DIM 512
#define H_DIM 256
#define HQ    (H_DIM / 4)   // 64 float4 per (b,t) row (1KB)
#define STAGES 32           // ring depth in t-steps; 32KB SMEM per block

__device__ __forceinline__ void cp_async16(void* smem, const void* gmem) {
    unsigned int s = (unsigned int)__cvta_generic_to_shared(smem);
    asm volatile("cp.async.cg.shared.global [%0], [%1], 16;" :: "r"(s), "l"(gmem));
}

__device__ __forceinline__ float4 lif_step(float4 v, float4 d, float4* z, float4 xv) {
    float4 nv, nz;
    nv.x = v.x * d.x * (1.0f - z->x) + xv.x;
    nv.y = v.y * d.y * (1.0f - z->y) + xv.y;
    nv.z = v.z * d.z * (1.0f - z->z) + xv.z;
    nv.w = v.w * d.w * (1.0f - z->w) + xv.w;
    nz.x = (nv.x > 0.5f) ? 1.0f : 0.0f;
    nz.y = (nv.y > 0.5f) ? 1.0f : 0.0f;
    nz.z = (nv.z > 0.5f) ? 1.0f : 0.0f;
    nz.w = (nv.w > 0.5f) ? 1.0f : 0.0f;
    *z = nz;
    return nv;
}

__global__ __launch_bounds__(32)
void lif_cpasync_kernel(const float4* __restrict__ x,
                        const float4* __restrict__ decay,
                        const float4* __restrict__ v0,
                        const float4* __restrict__ z0,
                        float4* __restrict__ out)
{
    __shared__ float4 buf[STAGES][HQ];   // 32 KB ring, 1KB (one t-row) per stage

    const int b = blockIdx.x;       // 0..511 — one warp per batch row
    const int q = threadIdx.x;      // 0..31; thread owns float4 slots q and q+32

    // sigmoid(decay) once per chain, correctly rounded via fp64
    const float4 dc0 = decay[q];
    const float4 dc1 = decay[q + 32];
    float4 d0, d1;
    d0.x = (float)(1.0 / (1.0 + exp(-(double)dc0.x)));
    d0.y = (float)(1.0 / (1.0 + exp(-(double)dc0.y)));
    d0.z = (float)(1.0 / (1.0 + exp(-(double)dc0.z)));
    d0.w = (float)(1.0 / (1.0 + exp(-(double)dc0.w)));
    d1.x = (float)(1.0 / (1.0 + exp(-(double)dc1.x)));
    d1.y = (float)(1.0 / (1.0 + exp(-(double)dc1.y)));
    d1.z = (float)(1.0 / (1.0 + exp(-(double)dc1.z)));
    d1.w = (float)(1.0 / (1.0 + exp(-(double)dc1.w)));

    const int bh = b * HQ + q;
    float4 v_0 = v0[bh];
    float4 v_1 = v0[bh + 32];
    float4 z_0 = z0[bh];
    float4 z_1 = z0[bh + 32];

    const size_t base = (size_t)b * T_DIM * HQ + q;
    const float4* __restrict__ xp = x + base;   // slot q; slot q+32 at +32
    float4* __restrict__ op = out + base;

    // Prologue: fill all STAGES stages (t = 0..31), one commit group per t.
    #pragma unroll 4
    for (int s = 0; s < STAGES; s++) {
        cp_async16(&buf[s][q],      xp + (size_t)s * HQ);
        cp_async16(&buf[s][q + 32], xp + (size_t)s * HQ + 32);
        asm volatile("cp.async.commit_group;" ::: "memory");
    }

    #pragma unroll 1
    for (int t = 0; t < T_DIM; t++) {
        // Group #t must be complete -> at most STAGES-1 groups outstanding.
        // Commits below are unconditional (empty groups allowed), so issued
        // count is always t'+STAGES and this bound is exact through the tail.
        asm volatile("cp.async.wait_group %0;" :: "n"(STAGES - 1) : "memory");

        const int slot = t & (STAGES - 1);
        float4 xv0 = buf[slot][q];
        float4 xv1 = buf[slot][q + 32];

        // (1-z) is exactly 0.0f or 1.0f -> rounding matches reference exactly
        v_0 = lif_step(v_0, d0, &z_0, xv0);
        v_1 = lif_step(v_1, d1, &z_1, xv1);
        __stcs(op + (size_t)t * HQ, z_0);
        __stcs(op + (size_t)t * HQ + 32, z_1);

        // Refill this slot for t+STAGES (thread-local addresses; the async
        // write lands >= one GMEM latency after the LDS above issued).
        const int t2 = t + STAGES;
        if (t2 < T_DIM) {
            cp_async16(&buf[slot][q],      xp + (size_t)t2 * HQ);
            cp_async16(&buf[slot][q + 32], xp + (size_t)t2 * HQ + 32);
        }
        asm volatile("cp.async.commit_group;" ::: "memory");
    }
}

extern "C" void kernel_launch(void* const* d_in, const int* in_sizes, int n_in,
                              void* d_out, int out_size)
{
    // Bind inputs BY SIZE (robust to metadata ordering):
    //   x: B*T*H   decay: H   v0,z0: B*H (both zero at runtime; order harmless)
    const float* x = 0;
    const float* decay = 0;
    const float* v0 = 0;
    const float* z0 = 0;

    const long long n_x  = (long long)B_DIM * T_DIM * H_DIM;
    const long long n_bh = (long long)B_DIM * H_DIM;

    for (int i = 0; i < n_in; i++) {
        long long n = in_sizes[i];
        if (n == n_x) {
            x = (const float*)d_in[i];
        } else if (n == H_DIM) {
            decay = (const float*)d_in[i];
        } else if (n == n_bh) {
            if (!v0) v0 = (const float*)d_in[i];
            else     z0 = (const float*)d_in[i];
        }
    }
    if (!x || !decay || !v0 || !z0) return;

    lif_cpasync_kernel<<<B_DIM, 32>>>(
        (const float4*)x, (const float4*)decay,
        (const float4*)v0, (const float4*)z0,
        (float4*)d_out);
}